// round 10
// baseline (speedup 1.0000x reference)
#include <cuda_runtime.h>
#include <cuda_bf16.h>
#include <cstdint>

// Problem (fixed shapes): N_NODES=50000, N_EDGES=800000, D_FEAT=64
//   out = segment_sum(x[src] * e, dst, N_NODES)
//
// Strategy (best-of measured rounds):
//   K1 (R9): fixed-capacity per-dst buckets, atomic cursor, 8 edges/thread
//       (MLP=8). Records hold (src*32, bits(w)) -> add-only gather address.
//   K2 (R5 shape): warp-per-node gather, ONE coalesced record load per 32
//       edges, register SHFL broadcast, 4-edge unroll (regs ~32, occ ~80%).
//   g_cnt zero-init BSS, self-reset by K2 -> no memset launch; replays see
//   zero counters every time.

#define N_NODES 50000
#define D_FEAT  64
#define CAP     96          // Poisson(16): P(deg>=96) ~ e^-92, guarded anyway

__device__ int  g_cnt[N_NODES];                    // zero-init, self-resetting
__device__ int2 g_bucket[(size_t)N_NODES * CAP];   // (src*32, bits(w))

// ------------------------------------------------------------ K1: scatter
__global__ void bucket_scatter_kernel(const float* __restrict__ e,
                                      const int*   __restrict__ src,
                                      const int*   __restrict__ dst,
                                      int n_edges) {
    int i0 = (blockIdx.x * blockDim.x + threadIdx.x) * 8;
    if (i0 + 7 < n_edges) {
        int4   da = *reinterpret_cast<const int4*>(dst + i0);
        int4   db = *reinterpret_cast<const int4*>(dst + i0 + 4);
        int4   sa = *reinterpret_cast<const int4*>(src + i0);
        int4   sb = *reinterpret_cast<const int4*>(src + i0 + 4);
        float4 ea = *reinterpret_cast<const float4*>(e + i0);
        float4 eb = *reinterpret_cast<const float4*>(e + i0 + 4);
        int   d[8] = {da.x, da.y, da.z, da.w, db.x, db.y, db.z, db.w};
        int   s[8] = {sa.x, sa.y, sa.z, sa.w, sb.x, sb.y, sb.z, sb.w};
        float w[8] = {ea.x, ea.y, ea.z, ea.w, eb.x, eb.y, eb.z, eb.w};
#pragma unroll
        for (int q = 0; q < 8; q++) {
            int pos = atomicAdd(&g_cnt[d[q]], 1);
            if (pos < CAP)
                g_bucket[(size_t)d[q] * CAP + pos] =
                    make_int2(s[q] * (D_FEAT / 2), __float_as_int(w[q]));
        }
    } else {
        for (int i = i0; i < n_edges; i++) {
            int dd  = dst[i];
            int pos = atomicAdd(&g_cnt[dd], 1);
            if (pos < CAP)
                g_bucket[(size_t)dd * CAP + pos] =
                    make_int2(src[i] * (D_FEAT / 2), __float_as_int(e[i]));
        }
    }
}

// ------------------------------------------------------------- K2: gather
// One warp per node; lane owns a float2 column. 4 edges per inner step
// (R5-proven: regs ~32 -> occ ~80%).
__global__ void gather_kernel(const float* __restrict__ x,
                              float* __restrict__ out,
                              int n_nodes) {
    int node = (blockIdx.x * blockDim.x + threadIdx.x) >> 5;
    int lane = threadIdx.x & 31;
    if (node >= n_nodes) return;

    int cnt = g_cnt[node];
    if (cnt > CAP) cnt = CAP;          // unreachable in practice

    const int2*   __restrict__ brow = g_bucket + (size_t)node * CAP;
    const float2* __restrict__ xl   = reinterpret_cast<const float2*>(x) + lane;

    float accx = 0.f, accy = 0.f;

    for (int base = 0; base < cnt; base += 32) {
        int idx = base + lane;
        // one coalesced record fetch per 32 edges; pad lanes are exact no-ops
        int2 rec = (idx < cnt) ? __ldg(&brow[idx]) : make_int2(0, 0);
        int m  = cnt - base; if (m > 32) m = 32;
        int mm = (m + 3) & ~3;          // pad to multiple of 4 (w=0 padding)

        for (int k = 0; k < mm; k += 4) {
            int s0 = __shfl_sync(0xffffffffu, rec.x, k + 0);
            int w0 = __shfl_sync(0xffffffffu, rec.y, k + 0);
            int s1 = __shfl_sync(0xffffffffu, rec.x, k + 1);
            int w1 = __shfl_sync(0xffffffffu, rec.y, k + 1);
            int s2 = __shfl_sync(0xffffffffu, rec.x, k + 2);
            int w2 = __shfl_sync(0xffffffffu, rec.y, k + 2);
            int s3 = __shfl_sync(0xffffffffu, rec.x, k + 3);
            int w3 = __shfl_sync(0xffffffffu, rec.y, k + 3);

            // 4 independent gathers in flight (src pre-multiplied by 32)
            float2 v0 = __ldg(xl + s0);
            float2 v1 = __ldg(xl + s1);
            float2 v2 = __ldg(xl + s2);
            float2 v3 = __ldg(xl + s3);

            accx = fmaf(v0.x, __int_as_float(w0), accx);
            accy = fmaf(v0.y, __int_as_float(w0), accy);
            accx = fmaf(v1.x, __int_as_float(w1), accx);
            accy = fmaf(v1.y, __int_as_float(w1), accy);
            accx = fmaf(v2.x, __int_as_float(w2), accx);
            accy = fmaf(v2.y, __int_as_float(w2), accy);
            accx = fmaf(v3.x, __int_as_float(w3), accx);
            accy = fmaf(v3.y, __int_as_float(w3), accy);
        }
    }

    // self-reset counter for the next graph replay (read happened above)
    if (lane == 0) g_cnt[node] = 0;

    float2 res; res.x = accx; res.y = accy;
    reinterpret_cast<float2*>(out)[(size_t)node * (D_FEAT / 2) + lane] = res;
}

extern "C" void kernel_launch(void* const* d_in, const int* in_sizes, int n_in,
                              void* d_out, int out_size) {
    // Identify inputs by element count:
    //   x : 3,200,000 floats; e, src, dst : 800,000 each in metadata order.
    const float* x   = nullptr;
    const float* e   = nullptr;
    const int*   src = nullptr;
    const int*   dst = nullptr;
    int n_edges = 0;

    int big_seen = 0;
    for (int i = 0; i < n_in; i++) {
        int sz = in_sizes[i];
        if (sz >= 1000000) {
            x = (const float*)d_in[i];
        } else if (sz >= 100000) {
            n_edges = sz;
            if (big_seen == 0)      e   = (const float*)d_in[i];
            else if (big_seen == 1) src = (const int*)d_in[i];
            else                    dst = (const int*)d_in[i];
            big_seen++;
        }
    }

    int n_nodes = out_size / D_FEAT;   // 50000

    const int B = 256;
    int scat_threads = (n_edges + 7) / 8;
    bucket_scatter_kernel<<<(scat_threads + B - 1) / B, B>>>(e, src, dst, n_edges);

    int total = n_nodes * 32;          // one warp per node
    gather_kernel<<<(total + B - 1) / B, B>>>(x, (float*)d_out, n_nodes);
}

// round 11
// speedup vs baseline: 1.0253x; 1.0253x over previous
#include <cuda_runtime.h>
#include <cuda_bf16.h>
#include <cstdint>

// Problem (fixed shapes): N_NODES=50000, N_EDGES=800000, D_FEAT=64
//   out = segment_sum(x[src] * e, dst, N_NODES)
//
// Strategy:
//   K1: fixed-capacity per-dst buckets, atomic cursor, 16 edges/thread
//       (MLP=16). Records hold (src*16, bits(w)) -> add-only float4 address.
//   K2: HALF-warp per node, float4 lanes: one LDG.128 serves one edge of
//       each of the warp's two nodes (instructions/edge halved vs R10,
//       8 independent x-loads in flight/warp). Records broadcast via
//       width-16 SHFL out of registers. No atomics in the hot pass.
//   g_cnt zero-init BSS, self-reset by K2 -> no memset launch.

#define N_NODES 50000
#define D_FEAT  64
#define F4      (D_FEAT / 4)   // 16 float4 per row
#define CAP     96             // Poisson(16): P(deg>=96) ~ e^-92, guarded anyway

__device__ int  g_cnt[N_NODES];                    // zero-init, self-resetting
__device__ int2 g_bucket[(size_t)N_NODES * CAP];   // (src*16, bits(w))

// ------------------------------------------------------------ K1: scatter
__global__ void bucket_scatter_kernel(const float* __restrict__ e,
                                      const int*   __restrict__ src,
                                      const int*   __restrict__ dst,
                                      int n_edges) {
    int i0 = (blockIdx.x * blockDim.x + threadIdx.x) * 16;
    if (i0 + 15 < n_edges) {
        int   d[16];
        int   s[16];
        float w[16];
#pragma unroll
        for (int c = 0; c < 4; c++) {
            int4   d4 = *reinterpret_cast<const int4*>(dst + i0 + 4 * c);
            int4   s4 = *reinterpret_cast<const int4*>(src + i0 + 4 * c);
            float4 e4 = *reinterpret_cast<const float4*>(e + i0 + 4 * c);
            d[4*c+0] = d4.x; d[4*c+1] = d4.y; d[4*c+2] = d4.z; d[4*c+3] = d4.w;
            s[4*c+0] = s4.x; s[4*c+1] = s4.y; s[4*c+2] = s4.z; s[4*c+3] = s4.w;
            w[4*c+0] = e4.x; w[4*c+1] = e4.y; w[4*c+2] = e4.z; w[4*c+3] = e4.w;
        }
#pragma unroll
        for (int q = 0; q < 16; q++) {
            int pos = atomicAdd(&g_cnt[d[q]], 1);
            if (pos < CAP)
                g_bucket[(size_t)d[q] * CAP + pos] =
                    make_int2(s[q] * F4, __float_as_int(w[q]));
        }
    } else {
        for (int i = i0; i < n_edges; i++) {
            int dd  = dst[i];
            int pos = atomicAdd(&g_cnt[dd], 1);
            if (pos < CAP)
                g_bucket[(size_t)dd * CAP + pos] =
                    make_int2(src[i] * F4, __float_as_int(e[i]));
        }
    }
}

// ------------------------------------------------------------- K2: gather
// Half-warp per node; lane owns a float4 column. Two independent node
// streams per warp -> 8 gathers in flight per warp.
__global__ void gather_kernel(const float* __restrict__ x,
                              float* __restrict__ out,
                              int n_nodes) {
    int warp = (blockIdx.x * blockDim.x + threadIdx.x) >> 5;
    int lane = threadIdx.x & 31;
    int half = lane >> 4;            // 0: node A, 1: node B
    int hl   = lane & 15;            // lane within half
    int node = warp * 2 + half;
    if (node >= n_nodes) return;

    int cnt = g_cnt[node];
    if (cnt > CAP) cnt = CAP;        // unreachable in practice
    // shared loop bound across the warp (pad lanes are exact no-ops)
    int cnt_loop = max(cnt, __shfl_xor_sync(0xffffffffu, cnt, 16));

    const int2*   __restrict__ brow = g_bucket + (size_t)node * CAP;
    const float4* __restrict__ xl   = reinterpret_cast<const float4*>(x) + hl;

    float4 acc = make_float4(0.f, 0.f, 0.f, 0.f);

    for (int base = 0; base < cnt_loop; base += 16) {
        int idx = base + hl;
        // coalesced record fetch: 16 records per half (128B contiguous)
        int2 rec = (idx < cnt) ? __ldg(&brow[idx]) : make_int2(0, 0);
        int m  = cnt_loop - base; if (m > 16) m = 16;
        int mm = (m + 3) & ~3;       // pad to multiple of 4

        for (int k = 0; k < mm; k += 4) {
            int s0 = __shfl_sync(0xffffffffu, rec.x, k + 0, 16);
            int w0 = __shfl_sync(0xffffffffu, rec.y, k + 0, 16);
            int s1 = __shfl_sync(0xffffffffu, rec.x, k + 1, 16);
            int w1 = __shfl_sync(0xffffffffu, rec.y, k + 1, 16);
            int s2 = __shfl_sync(0xffffffffu, rec.x, k + 2, 16);
            int w2 = __shfl_sync(0xffffffffu, rec.y, k + 2, 16);
            int s3 = __shfl_sync(0xffffffffu, rec.x, k + 3, 16);
            int w3 = __shfl_sync(0xffffffffu, rec.y, k + 3, 16);

            // 4 loads/half = 8 independent edge gathers in flight per warp
            float4 v0 = __ldg(xl + s0);
            float4 v1 = __ldg(xl + s1);
            float4 v2 = __ldg(xl + s2);
            float4 v3 = __ldg(xl + s3);

            float f0 = __int_as_float(w0);
            float f1 = __int_as_float(w1);
            float f2 = __int_as_float(w2);
            float f3 = __int_as_float(w3);

            acc.x = fmaf(v0.x, f0, acc.x);  acc.y = fmaf(v0.y, f0, acc.y);
            acc.z = fmaf(v0.z, f0, acc.z);  acc.w = fmaf(v0.w, f0, acc.w);
            acc.x = fmaf(v1.x, f1, acc.x);  acc.y = fmaf(v1.y, f1, acc.y);
            acc.z = fmaf(v1.z, f1, acc.z);  acc.w = fmaf(v1.w, f1, acc.w);
            acc.x = fmaf(v2.x, f2, acc.x);  acc.y = fmaf(v2.y, f2, acc.y);
            acc.z = fmaf(v2.z, f2, acc.z);  acc.w = fmaf(v2.w, f2, acc.w);
            acc.x = fmaf(v3.x, f3, acc.x);  acc.y = fmaf(v3.y, f3, acc.y);
            acc.z = fmaf(v3.z, f3, acc.z);  acc.w = fmaf(v3.w, f3, acc.w);
        }
    }

    // self-reset counter for the next graph replay
    if (hl == 0) g_cnt[node] = 0;

    reinterpret_cast<float4*>(out)[(size_t)node * F4 + hl] = acc;
}

extern "C" void kernel_launch(void* const* d_in, const int* in_sizes, int n_in,
                              void* d_out, int out_size) {
    // Identify inputs by element count:
    //   x : 3,200,000 floats; e, src, dst : 800,000 each in metadata order.
    const float* x   = nullptr;
    const float* e   = nullptr;
    const int*   src = nullptr;
    const int*   dst = nullptr;
    int n_edges = 0;

    int big_seen = 0;
    for (int i = 0; i < n_in; i++) {
        int sz = in_sizes[i];
        if (sz >= 1000000) {
            x = (const float*)d_in[i];
        } else if (sz >= 100000) {
            n_edges = sz;
            if (big_seen == 0)      e   = (const float*)d_in[i];
            else if (big_seen == 1) src = (const int*)d_in[i];
            else                    dst = (const int*)d_in[i];
            big_seen++;
        }
    }

    int n_nodes = out_size / D_FEAT;   // 50000

    const int B = 256;
    int scat_threads = (n_edges + 15) / 16;
    bucket_scatter_kernel<<<(scat_threads + B - 1) / B, B>>>(e, src, dst, n_edges);

    int total = n_nodes * 16;          // half-warp per node
    gather_kernel<<<(total + B - 1) / B, B>>>(x, (float*)d_out, n_nodes);
}

// round 12
// speedup vs baseline: 1.0653x; 1.0390x over previous
#include <cuda_runtime.h>
#include <cuda_bf16.h>
#include <cstdint>

// Problem (fixed shapes): N_NODES=50000, N_EDGES=800000, D_FEAT=64
//   out = segment_sum(x[src] * e, dst, N_NODES)
//
// Strategy:
//   K1: fixed-capacity per-dst buckets, atomic cursor, 16 edges/thread.
//       Records hold (src*16, bits(w)) -> add-only float4 gather address.
//   K2: ONE WARP PER NODE, organized as 2 edge-slots x 16 float4-lanes.
//       Both halves process the SAME node, interleaved even/odd records
//       (balanced, trip count = deg/2 per half), 8 independent LDG.128
//       x-gathers in flight per warp, final cross-half shfl reduction.
//   g_cnt zero-init BSS, self-reset by K2 -> no memset launch.

#define N_NODES 50000
#define D_FEAT  64
#define F4      (D_FEAT / 4)   // 16 float4 per row
#define CAP     96             // Poisson(16): P(deg>=96) ~ e^-92, guarded anyway

__device__ int  g_cnt[N_NODES];                    // zero-init, self-resetting
__device__ int2 g_bucket[(size_t)N_NODES * CAP];   // (src*16, bits(w))

// ------------------------------------------------------------ K1: scatter
__global__ void bucket_scatter_kernel(const float* __restrict__ e,
                                      const int*   __restrict__ src,
                                      const int*   __restrict__ dst,
                                      int n_edges) {
    int i0 = (blockIdx.x * blockDim.x + threadIdx.x) * 16;
    if (i0 + 15 < n_edges) {
        int   d[16];
        int   s[16];
        float w[16];
#pragma unroll
        for (int c = 0; c < 4; c++) {
            int4   d4 = *reinterpret_cast<const int4*>(dst + i0 + 4 * c);
            int4   s4 = *reinterpret_cast<const int4*>(src + i0 + 4 * c);
            float4 e4 = *reinterpret_cast<const float4*>(e + i0 + 4 * c);
            d[4*c+0] = d4.x; d[4*c+1] = d4.y; d[4*c+2] = d4.z; d[4*c+3] = d4.w;
            s[4*c+0] = s4.x; s[4*c+1] = s4.y; s[4*c+2] = s4.z; s[4*c+3] = s4.w;
            w[4*c+0] = e4.x; w[4*c+1] = e4.y; w[4*c+2] = e4.z; w[4*c+3] = e4.w;
        }
#pragma unroll
        for (int q = 0; q < 16; q++) {
            int pos = atomicAdd(&g_cnt[d[q]], 1);
            if (pos < CAP)
                g_bucket[(size_t)d[q] * CAP + pos] =
                    make_int2(s[q] * F4, __float_as_int(w[q]));
        }
    } else {
        for (int i = i0; i < n_edges; i++) {
            int dd  = dst[i];
            int pos = atomicAdd(&g_cnt[dd], 1);
            if (pos < CAP)
                g_bucket[(size_t)dd * CAP + pos] =
                    make_int2(src[i] * F4, __float_as_int(e[i]));
        }
    }
}

// ------------------------------------------------------------- K2: gather
// Warp per node; half h handles records 2k+h of each 32-record chunk.
__global__ void gather_kernel(const float* __restrict__ x,
                              float* __restrict__ out,
                              int n_nodes) {
    int node = (blockIdx.x * blockDim.x + threadIdx.x) >> 5;
    int lane = threadIdx.x & 31;
    int half = lane >> 4;            // edge-slot parity
    int hl   = lane & 15;            // float4 column index
    if (node >= n_nodes) return;

    int cnt = g_cnt[node];
    if (cnt > CAP) cnt = CAP;        // unreachable in practice

    const int2*   __restrict__ brow = g_bucket + (size_t)node * CAP;
    const float4* __restrict__ xl   = reinterpret_cast<const float4*>(x) + hl;

    float4 acc = make_float4(0.f, 0.f, 0.f, 0.f);

    for (int base = 0; base < cnt; base += 32) {
        int idx = base + lane;
        // one coalesced record fetch per 32 edges; pad lanes are exact no-ops
        int2 rec = (idx < cnt) ? __ldg(&brow[idx]) : make_int2(0, 0);
        int m  = cnt - base; if (m > 32) m = 32;
        int hc = (m + 1) >> 1;        // edges for half 0 (>= half 1's count)
        int mm = (hc + 3) & ~3;       // pad to multiple of 4 (zero records)

        for (int k = 0; k < mm; k += 4) {
            // record lane for slot j: 2*(k+j)+half  (always < 32)
            int r0 = 2 * (k + 0) + half;
            int r1 = 2 * (k + 1) + half;
            int r2 = 2 * (k + 2) + half;
            int r3 = 2 * (k + 3) + half;

            int s0 = __shfl_sync(0xffffffffu, rec.x, r0);
            int w0 = __shfl_sync(0xffffffffu, rec.y, r0);
            int s1 = __shfl_sync(0xffffffffu, rec.x, r1);
            int w1 = __shfl_sync(0xffffffffu, rec.y, r1);
            int s2 = __shfl_sync(0xffffffffu, rec.x, r2);
            int w2 = __shfl_sync(0xffffffffu, rec.y, r2);
            int s3 = __shfl_sync(0xffffffffu, rec.x, r3);
            int w3 = __shfl_sync(0xffffffffu, rec.y, r3);

            // 8 independent LDG.128 gathers in flight per warp (4 per half)
            float4 v0 = __ldg(xl + s0);
            float4 v1 = __ldg(xl + s1);
            float4 v2 = __ldg(xl + s2);
            float4 v3 = __ldg(xl + s3);

            float f0 = __int_as_float(w0);
            float f1 = __int_as_float(w1);
            float f2 = __int_as_float(w2);
            float f3 = __int_as_float(w3);

            acc.x = fmaf(v0.x, f0, acc.x);  acc.y = fmaf(v0.y, f0, acc.y);
            acc.z = fmaf(v0.z, f0, acc.z);  acc.w = fmaf(v0.w, f0, acc.w);
            acc.x = fmaf(v1.x, f1, acc.x);  acc.y = fmaf(v1.y, f1, acc.y);
            acc.z = fmaf(v1.z, f1, acc.z);  acc.w = fmaf(v1.w, f1, acc.w);
            acc.x = fmaf(v2.x, f2, acc.x);  acc.y = fmaf(v2.y, f2, acc.y);
            acc.z = fmaf(v2.z, f2, acc.z);  acc.w = fmaf(v2.w, f2, acc.w);
            acc.x = fmaf(v3.x, f3, acc.x);  acc.y = fmaf(v3.y, f3, acc.y);
            acc.z = fmaf(v3.z, f3, acc.z);  acc.w = fmaf(v3.w, f3, acc.w);
        }
    }

    // combine the two edge-slot halves (lanes hl and hl+16 hold same columns)
    acc.x += __shfl_xor_sync(0xffffffffu, acc.x, 16);
    acc.y += __shfl_xor_sync(0xffffffffu, acc.y, 16);
    acc.z += __shfl_xor_sync(0xffffffffu, acc.z, 16);
    acc.w += __shfl_xor_sync(0xffffffffu, acc.w, 16);

    // self-reset counter for the next graph replay
    if (lane == 0) g_cnt[node] = 0;

    if (half == 0)
        reinterpret_cast<float4*>(out)[(size_t)node * F4 + hl] = acc;
}

extern "C" void kernel_launch(void* const* d_in, const int* in_sizes, int n_in,
                              void* d_out, int out_size) {
    // Identify inputs by element count:
    //   x : 3,200,000 floats; e, src, dst : 800,000 each in metadata order.
    const float* x   = nullptr;
    const float* e   = nullptr;
    const int*   src = nullptr;
    const int*   dst = nullptr;
    int n_edges = 0;

    int big_seen = 0;
    for (int i = 0; i < n_in; i++) {
        int sz = in_sizes[i];
        if (sz >= 1000000) {
            x = (const float*)d_in[i];
        } else if (sz >= 100000) {
            n_edges = sz;
            if (big_seen == 0)      e   = (const float*)d_in[i];
            else if (big_seen == 1) src = (const int*)d_in[i];
            else                    dst = (const int*)d_in[i];
            big_seen++;
        }
    }

    int n_nodes = out_size / D_FEAT;   // 50000

    const int B = 256;
    int scat_threads = (n_edges + 15) / 16;
    bucket_scatter_kernel<<<(scat_threads + B - 1) / B, B>>>(e, src, dst, n_edges);

    int total = n_nodes * 32;          // one warp per node
    gather_kernel<<<(total + B - 1) / B, B>>>(x, (float*)d_out, n_nodes);
}